// round 14
// baseline (speedup 1.0000x reference)
#include <cuda_runtime.h>

// FraudDetectionModel R14: single graph node, SHFL-distributed params.
//  Structural findings: LDC-param kernels hit the 32.3us HBM floor but need
//  a 2nd node (+4.2us); smem-param single-node = 34.2+1.0. This kernel keeps
//  ONE node and routes params through NEITHER L1tex nor a CTA barrier:
//  per warp, lanes 0..26 fold one param each (one-time LDGs, L1-resident
//  after wave 1), and the mainloop broadcasts them via __shfl_sync (SHFL
//  pipe, separate from the LSU/L1tex data stream). No smem, no barrier.

#define BATCH   16777216
#define THREADS 256
#define ROWS_PER_THREAD 4
#define FULLMASK 0xffffffffu

__device__ __forceinline__ float fast_tanh(float x) {
    float y;
    asm("tanh.approx.f32 %0, %1;" : "=f"(y) : "f"(x));
    return y;
}

__global__ void __launch_bounds__(THREADS)
fraud_mlp_kernel(const float4* __restrict__ x,    // [B/2] row pairs
                 float4*       __restrict__ out,  // [B/4] quad outputs
                 const float*  __restrict__ Ws,   // [4,2,2]
                 const float*  __restrict__ bs,   // [4,2]
                 const float*  __restrict__ sc,   // [4,2]
                 const float*  __restrict__ sh,   // [4,2]
                 const float*  __restrict__ Wf,   // [1,2]
                 const float*  __restrict__ bf)   // [1]
{
    const int i = blockIdx.x * blockDim.x + threadIdx.x;

    // Data loads first: independent of the fold, overlap its LDG latency.
    const float4 xv0 = x[2 * i + 0];   // rows 0,1
    const float4 xv1 = x[2 * i + 1];   // rows 2,3

    // ---- in-warp lane fold: lane j (<27) computes folded param j ----
    // layout: layer l at [6l]: w00 w01 w10 w11 b0 b1 ; 24..26 = wf0' wf1' bf'
    const int lane = threadIdx.x & 31;
    float v = 0.0f;
    if (lane < 27) {
        if (lane < 24) {
            const int l = lane / 6;       // layer 0..3
            const int j = lane % 6;       // 0..3 W, 4..5 bias
            if (l == 0) {
                v = (j < 4) ? __ldg(Ws + j) : __ldg(bs + (j - 4));
            } else if (j < 4) {
                // W'_l[j] = W_l[j] * s_{l-1}[col(j)]
                v = __ldg(Ws + l * 4 + j) * __ldg(sc + (l - 1) * 2 + (j & 1));
            } else {
                // b'_l[row] = W_l[row,:].t_{l-1} + b_l[row]
                const int row = j - 4;
                v = fmaf(__ldg(Ws + l * 4 + row * 2 + 0), __ldg(sh + (l - 1) * 2 + 0),
                    fmaf(__ldg(Ws + l * 4 + row * 2 + 1), __ldg(sh + (l - 1) * 2 + 1),
                         __ldg(bs + l * 2 + row)));
            }
        } else if (lane == 24) {
            v = __ldg(Wf + 0) * __ldg(sc + 6);
        } else if (lane == 25) {
            v = __ldg(Wf + 1) * __ldg(sc + 7);
        } else { // lane == 26
            v = fmaf(__ldg(Wf + 0), __ldg(sh + 6),
                fmaf(__ldg(Wf + 1), __ldg(sh + 7), __ldg(bf)));
        }
    }
    // All lanes reconverge here; v holds param[lane] for lane < 27.

    float ha[4], hb[4];
    ha[0] = xv0.x; hb[0] = xv0.y;  ha[1] = xv0.z; hb[1] = xv0.w;
    ha[2] = xv1.x; hb[2] = xv1.y;  ha[3] = xv1.z; hb[3] = xv1.w;

    // folded chain: h <- tanh(W' h + b'); per-layer params via 6 SHFLs
#pragma unroll
    for (int l = 0; l < 4; l++) {
        const float w00 = __shfl_sync(FULLMASK, v, l * 6 + 0);
        const float w01 = __shfl_sync(FULLMASK, v, l * 6 + 1);
        const float w10 = __shfl_sync(FULLMASK, v, l * 6 + 2);
        const float w11 = __shfl_sync(FULLMASK, v, l * 6 + 3);
        const float b0  = __shfl_sync(FULLMASK, v, l * 6 + 4);
        const float b1  = __shfl_sync(FULLMASK, v, l * 6 + 5);
#pragma unroll
        for (int r = 0; r < 4; r++) {
            float u0 = fmaf(w00, ha[r], fmaf(w01, hb[r], b0));
            float u1 = fmaf(w10, ha[r], fmaf(w11, hb[r], b1));
            ha[r] = fast_tanh(u0);
            hb[r] = fast_tanh(u1);
        }
    }

    const float wf0 = __shfl_sync(FULLMASK, v, 24);
    const float wf1 = __shfl_sync(FULLMASK, v, 25);
    const float bff = __shfl_sync(FULLMASK, v, 26);

    float4 o;
    o.x = fmaf(wf0, ha[0], fmaf(wf1, hb[0], bff));
    o.y = fmaf(wf0, ha[1], fmaf(wf1, hb[1], bff));
    o.z = fmaf(wf0, ha[2], fmaf(wf1, hb[2], bff));
    o.w = fmaf(wf0, ha[3], fmaf(wf1, hb[3], bff));

    out[i] = o;
}

extern "C" void kernel_launch(void* const* d_in, const int* in_sizes, int n_in,
                              void* d_out, int out_size)
{
    const float4* x = (const float4*)d_in[0];
    float4* out = (float4*)d_out;

    const int nthreads = BATCH / ROWS_PER_THREAD;   // 4,194,304
    const int blocks = nthreads / THREADS;          // 16384
    fraud_mlp_kernel<<<blocks, THREADS>>>(
        x, out,
        (const float*)d_in[1], (const float*)d_in[2], (const float*)d_in[3],
        (const float*)d_in[4], (const float*)d_in[5], (const float*)d_in[6]);
}